// round 3
// baseline (speedup 1.0000x reference)
#include <cuda_runtime.h>

#define BATCH 64
#define KPTS  2048
#define NTHR  128
#define RI    4
#define TI    (NTHR * RI)          // 512 query points per block
#define NI    (KPTS / TI)          // 4 i-chunks
#define NJ    2                    // j chunks
#define TJ    (KPTS / NJ)          // 1024 tile points
#define NE    (2 * BATCH * KPTS)   // 262144 (dir, b, i) entries
#define INF_BITS 0x7f800000

typedef unsigned long long ull;

// partial minima: [jc][dir][b][i]  (plain stores, no atomics, no init needed)
__device__ float g_pm[NJ * NE];
__device__ float g_part[256];
__device__ unsigned int g_ticket;   // zero-initialized; last reduce block resets it

// ---------- f32x2 packed helpers ----------
__device__ __forceinline__ ull pk(float a, float b) {
    ull r; asm("mov.b64 %0, {%1,%2};" : "=l"(r) : "f"(a), "f"(b)); return r;
}
__device__ __forceinline__ void upk(ull v, float& a, float& b) {
    asm("mov.b64 {%0,%1}, %2;" : "=f"(a), "=f"(b) : "l"(v));
}
__device__ __forceinline__ ull fma2(ull a, ull b, ull c) {
    ull d; asm("fma.rn.f32x2 %0, %1, %2, %3;" : "=l"(d) : "l"(a), "l"(b), "l"(c)); return d;
}

// ---------- main: broadcast pass, one (i-chunk, j-chunk, dir, batch) per block ----------
__global__ void __launch_bounds__(NTHR)
chamfer_pass(const float* __restrict__ P, const float* __restrict__ T) {
    __shared__ ulonglong2 sA[TJ];   // {(-2bx,-2bx),(-2by,-2by)}  16 KB
    __shared__ ull        sB[TJ];   // {b2,b2}                     8 KB

    const int jc  = blockIdx.y >> 1;
    const int dir = blockIdx.y & 1;        // 0: query=P tile=T ; 1: swapped
    const int b   = blockIdx.z;
    const int tid = threadIdx.x;

    const float* Ap = (dir ? T : P) + b * (2 * KPTS);  // query side
    const float* Bp = (dir ? P : T) + b * (2 * KPTS);  // tile side
    const int jbase = jc * TJ;

    // stage tile (1024 points, coalesced)
    for (int t = tid; t < TJ; t += NTHR) {
        float bx = Bp[jbase + t];
        float by = Bp[KPTS + jbase + t];
        float m2x = -2.0f * bx, m2y = -2.0f * by;
        sA[t] = make_ulonglong2(pk(m2x, m2x), pk(m2y, m2y));
        float b2 = bx * bx + by * by;
        sB[t] = pk(b2, b2);
    }

    // query points: 4 consecutive i per thread, vectorized load
    const int i0 = blockIdx.x * TI + tid * RI;
    float4 x4 = *reinterpret_cast<const float4*>(Ap + i0);
    float4 y4 = *reinterpret_cast<const float4*>(Ap + KPTS + i0);
    ull px01 = pk(x4.x, x4.y), px23 = pk(x4.z, x4.w);
    ull py01 = pk(y4.x, y4.y), py23 = pk(y4.z, y4.w);

    const float FINF = __int_as_float(INF_BITS);
    float r0 = FINF, r1 = FINF, r2 = FINF, r3 = FINF;

    __syncthreads();

#pragma unroll 16
    for (int j = 0; j < TJ; ++j) {
        ulonglong2 Aj = sA[j];     // broadcast LDS.128
        ull        c2 = sB[j];     // broadcast LDS.64

        ull v0 = fma2(py01, Aj.y, fma2(px01, Aj.x, c2));
        ull v1 = fma2(py23, Aj.y, fma2(px23, Aj.x, c2));

        float a, bb, c, d;
        upk(v0, a, bb); upk(v1, c, d);
        r0 = fminf(r0, a); r1 = fminf(r1, bb);
        r2 = fminf(r2, c); r3 = fminf(r3, d);
    }

    // fold a2, publish partial min d^2 (raw float, may be tiny-negative)
    float p2a = x4.x * x4.x + y4.x * y4.x;
    float p2b = x4.y * x4.y + y4.y * y4.y;
    float p2c = x4.z * x4.z + y4.z * y4.z;
    float p2d = x4.w * x4.w + y4.w * y4.w;

    float4 out = make_float4(p2a + r0, p2b + r1, p2c + r2, p2d + r3);
    int e = (dir * BATCH + b) * KPTS + i0;              // entry index
    *reinterpret_cast<float4*>(&g_pm[jc * NE + e]) = out;
}

// ---------- fused reduce: min over jc, clamp, sqrt, sum; last block finalizes ----------
#define RBLK 256
#define RTHR 256
__global__ void __launch_bounds__(RTHR)
reduce_all(float* out) {
    __shared__ float ss[RTHR];
    const int tid = threadIdx.x;
    const int base = (blockIdx.x * RTHR + tid) * 4;     // 4 elems/thread

    float4 a = *reinterpret_cast<const float4*>(&g_pm[base]);
    float4 c = *reinterpret_cast<const float4*>(&g_pm[NE + base]);
    float s = sqrtf(fmaxf(fminf(a.x, c.x), 0.0f))
            + sqrtf(fmaxf(fminf(a.y, c.y), 0.0f))
            + sqrtf(fmaxf(fminf(a.z, c.z), 0.0f))
            + sqrtf(fmaxf(fminf(a.w, c.w), 0.0f));

    ss[tid] = s;
    __syncthreads();
#pragma unroll
    for (int st = RTHR / 2; st > 0; st >>= 1) {
        if (tid < st) ss[tid] += ss[tid + st];
        __syncthreads();
    }

    __shared__ bool amLast;
    if (tid == 0) {
        g_part[blockIdx.x] = ss[0];
        __threadfence();
        unsigned int t = atomicAdd(&g_ticket, 1u);
        amLast = (t == RBLK - 1);
    }
    __syncthreads();

    if (amLast) {
        float v = g_part[tid];          // RTHR == RBLK: one partial per thread
        ss[tid] = v;
        __syncthreads();
#pragma unroll
        for (int st = RTHR / 2; st > 0; st >>= 1) {
            if (tid < st) ss[tid] += ss[tid + st];
            __syncthreads();
        }
        if (tid == 0) {
            out[0] = ss[0] * (1.0f / (float)(BATCH * KPTS));
            g_ticket = 0;               // reset for next graph replay
        }
    }
}

extern "C" void kernel_launch(void* const* d_in, const int* in_sizes, int n_in,
                              void* d_out, int out_size) {
    const float* P = (const float*)d_in[0];   // predicted (64, 4096)
    const float* T = (const float*)d_in[1];   // target    (64, 4096)
    (void)in_sizes; (void)n_in; (void)out_size;

    dim3 grid(NI, 2 * NJ, BATCH);             // 4 x 4 x 64 = 1024 blocks
    chamfer_pass<<<grid, NTHR>>>(P, T);
    reduce_all<<<RBLK, RTHR>>>((float*)d_out);
}

// round 5
// speedup vs baseline: 1.8341x; 1.8341x over previous
#include <cuda_runtime.h>

#define BATCH 64
#define KPTS  2048
#define NTHR  128
#define RI    4
#define TI    (NTHR * RI)          // 512 query (P) points per block
#define NI    (KPTS / TI)          // 4 i-chunks
#define TJ    512                  // target (T) tile per block
#define NJ    (KPTS / TJ)          // 4 j-chunks
#define DUP   64                   // wrap duplication for lane-staggered j
#define NENT  (BATCH * KPTS)       // 131072 entries per side
#define INF_BITS 0x7f800000
#define RBLK  512
#define RTHR  256

typedef unsigned long long ull;

// partial minima (plain stores -> no init kernel, no global atomics)
__device__ float g_rowp[NJ * NENT];   // [jc][b*KPTS + i]   min over j-chunk
__device__ int   g_colp[NI * NENT];   // [ic][b*KPTS + j]   min over i-chunk (float bits)
__device__ float g_part[RBLK];
__device__ unsigned int g_ticket;     // zero-init; last reduce block resets

// ---------- f32x2 packed helpers ----------
__device__ __forceinline__ ull pk(float a, float b) {
    ull r; asm("mov.b64 %0, {%1,%2};" : "=l"(r) : "f"(a), "f"(b)); return r;
}
__device__ __forceinline__ void upk(ull v, float& a, float& b) {
    asm("mov.b64 {%0,%1}, %2;" : "=f"(a), "=f"(b) : "l"(v));
}
__device__ __forceinline__ ull fma2(ull a, ull b, ull c) {
    ull d; asm("fma.rn.f32x2 %0, %1, %2, %3;" : "=l"(d) : "l"(a), "l"(b), "l"(c)); return d;
}
__device__ __forceinline__ ull add2(ull a, ull b) {
    ull d; asm("add.rn.f32x2 %0, %1, %2;" : "=l"(d) : "l"(a), "l"(b)); return d;
}

// ---------- main: single visit per pair, both directions ----------
// w_ij = d2_ij = p2_i + t2_j - 2 px_i tx_j - 2 py_i ty_j   (fp, may be tiny-neg)
// rowmin_i (registers) and colmin_j (smem s32-min on float bits; s32 ordering
// prefers negatives, which clamp to 0 later == reference's clamped min).
__global__ void __launch_bounds__(NTHR)
chamfer_main(const float* __restrict__ P, const float* __restrict__ T) {
    __shared__ ulonglong2 sA[TJ + DUP];   // {(-2tx,-2tx), (-2ty,-2ty)}
    __shared__ ull        sB[TJ + DUP];   // {t2, t2}
    __shared__ int        sCol[TJ + DUP]; // partial colmin bits

    const int b   = blockIdx.z;
    const int ic  = blockIdx.y;
    const int jc  = blockIdx.x;
    const int tid = threadIdx.x;

    const float* Pb = P + b * (2 * KPTS);
    const float* Tb = T + b * (2 * KPTS);
    const int jbase = jc * TJ;

    // stage target tile (with DUP-entry wrap duplication)
    for (int t = tid; t < TJ + DUP; t += NTHR) {
        int j = jbase + (t & (TJ - 1));
        float tx = Tb[j];
        float ty = Tb[KPTS + j];
        float m2x = -2.0f * tx, m2y = -2.0f * ty;
        sA[t] = make_ulonglong2(pk(m2x, m2x), pk(m2y, m2y));
        float t2 = tx * tx + ty * ty;
        sB[t] = pk(t2, t2);
        sCol[t] = INF_BITS;
    }

    // per-thread predicted points (4 consecutive i, vectorized load)
    const int i0 = ic * TI + tid * RI;
    float4 x4 = *reinterpret_cast<const float4*>(Pb + i0);
    float4 y4 = *reinterpret_cast<const float4*>(Pb + KPTS + i0);
    ull px01 = pk(x4.x, x4.y), px23 = pk(x4.z, x4.w);
    ull py01 = pk(y4.x, y4.y), py23 = pk(y4.z, y4.w);
    float p2a = x4.x * x4.x + y4.x * y4.x;
    float p2b = x4.y * x4.y + y4.y * y4.y;
    float p2c = x4.z * x4.z + y4.z * y4.z;
    float p2d = x4.w * x4.w + y4.w * y4.w;
    ull pp01 = pk(p2a, p2b), pp23 = pk(p2c, p2d);

    const float FINF = __int_as_float(INF_BITS);
    float r0 = FINF, r1 = FINF, r2 = FINF, r3 = FINF;

    // lane-staggered start: intra-warp distinct j (conflict-free LDS + spread ATOMS)
    const int off = (tid & 31) + ((tid >> 5) << 3);   // 0..55 (< DUP)

    __syncthreads();

#pragma unroll 8
    for (int jt = 0; jt < TJ; ++jt) {
        const int idx = off + jt;
        ulonglong2 A = sA[idx];      // LDS.128
        ull c2       = sB[idx];      // LDS.64

        // fold p2 into the addend: w = full d^2 serves BOTH minima
        ull c01 = add2(c2, pp01);
        ull c23 = add2(c2, pp23);
        ull w0 = fma2(py01, A.y, fma2(px01, A.x, c01));
        ull w1 = fma2(py23, A.y, fma2(px23, A.x, c23));

        float a, bb, c, d;
        upk(w0, a, bb); upk(w1, c, d);
        r0 = fminf(r0, a); r1 = fminf(r1, bb);
        r2 = fminf(r2, c); r3 = fminf(r3, d);

        float m = fminf(fminf(a, bb), fminf(c, d));
        atomicMin(&sCol[idx], __float_as_int(m));   // spread-address ATOMS
    }

    __syncthreads();

    // fold wrap duplicates back (exclusive after barrier)
    if (tid < DUP) {
        int v = sCol[TJ + tid];
        if (v < sCol[tid]) sCol[tid] = v;
    }
    __syncthreads();

    // publish block partials (plain stores into per-chunk slabs)
    for (int t = tid; t < TJ; t += NTHR)
        g_colp[ic * NENT + b * KPTS + jbase + t] = sCol[t];

    *reinterpret_cast<float4*>(&g_rowp[jc * NENT + b * KPTS + i0]) =
        make_float4(r0, r1, r2, r3);
}

// ---------- fused reduce: min over chunks, clamp, sqrt, sum; ticketed final ----------
__global__ void __launch_bounds__(RTHR)
reduce_all(float* out) {
    __shared__ float ss[RTHR];
    const int tid = threadIdx.x;
    const long long e = ((long long)blockIdx.x * RTHR + tid) * 2;  // 2 entries/thread

    float s;
    if (e < NENT) {        // row side (whole block uniform: 256 row blocks first)
        float2 m = *reinterpret_cast<const float2*>(&g_rowp[e]);
#pragma unroll
        for (int c = 1; c < NJ; ++c) {
            float2 v = *reinterpret_cast<const float2*>(&g_rowp[c * NENT + e]);
            m.x = fminf(m.x, v.x); m.y = fminf(m.y, v.y);
        }
        s = sqrtf(fmaxf(m.x, 0.0f)) + sqrtf(fmaxf(m.y, 0.0f));
    } else {               // col side
        long long e2 = e - NENT;
        int2 m = *reinterpret_cast<const int2*>(&g_colp[e2]);
#pragma unroll
        for (int c = 1; c < NI; ++c) {
            int2 v = *reinterpret_cast<const int2*>(&g_colp[c * NENT + e2]);
            m.x = min(m.x, v.x); m.y = min(m.y, v.y);
        }
        s = sqrtf(fmaxf(__int_as_float(m.x), 0.0f))
          + sqrtf(fmaxf(__int_as_float(m.y), 0.0f));
    }

    ss[tid] = s;
    __syncthreads();
#pragma unroll
    for (int st = RTHR / 2; st > 0; st >>= 1) {
        if (tid < st) ss[tid] += ss[tid + st];
        __syncthreads();
    }

    __shared__ bool amLast;
    if (tid == 0) {
        g_part[blockIdx.x] = ss[0];
        __threadfence();
        unsigned int t = atomicAdd(&g_ticket, 1u);
        amLast = (t == RBLK - 1);
    }
    __syncthreads();

    if (amLast) {
        __threadfence();
        ss[tid] = g_part[tid] + g_part[tid + RTHR];
        __syncthreads();
#pragma unroll
        for (int st = RTHR / 2; st > 0; st >>= 1) {
            if (tid < st) ss[tid] += ss[tid + st];
            __syncthreads();
        }
        if (tid == 0) {
            out[0] = ss[0] * (1.0f / (float)(BATCH * KPTS));
            g_ticket = 0;               // reset for next graph replay
        }
    }
}

extern "C" void kernel_launch(void* const* d_in, const int* in_sizes, int n_in,
                              void* d_out, int out_size) {
    const float* P = (const float*)d_in[0];   // predicted (64, 4096)
    const float* T = (const float*)d_in[1];   // target    (64, 4096)
    (void)in_sizes; (void)n_in; (void)out_size;

    dim3 grid(NJ, NI, BATCH);                 // 4 x 4 x 64 = 1024 blocks
    chamfer_main<<<grid, NTHR>>>(P, T);
    reduce_all<<<RBLK, RTHR>>>((float*)d_out);
}